// round 16
// baseline (speedup 1.0000x reference)
#include <cuda_runtime.h>
#include <cuda_fp16.h>
#include <math.h>
#include <stdint.h>

#define Bsz 4
#define SEQ 2048
#define HID 1024
#define NH 16
#define HD 64

// fp16 scratch
__device__ __half g_q[Bsz*NH*SEQ*HD];
__device__ __half g_k[Bsz*NH*SEQ*HD];
__device__ __half g_v[Bsz*NH*SEQ*HD];
__device__ __half g_xh[(size_t)Bsz*SEQ*HID];
__device__ __half g_wh[3*HID*HID];

// ---------------------------------------------------------------------------
__device__ __forceinline__ uint32_t sptr(const void* p) {
    return (uint32_t)__cvta_generic_to_shared(p);
}
__device__ __forceinline__ void ldsm4(uint32_t* r, uint32_t a) {
    asm volatile("ldmatrix.sync.aligned.m8n8.x4.shared.b16 {%0,%1,%2,%3}, [%4];"
        : "=r"(r[0]), "=r"(r[1]), "=r"(r[2]), "=r"(r[3]) : "r"(a));
}
__device__ __forceinline__ void ldsm4t(uint32_t* r, uint32_t a) {
    asm volatile("ldmatrix.sync.aligned.m8n8.x4.trans.shared.b16 {%0,%1,%2,%3}, [%4];"
        : "=r"(r[0]), "=r"(r[1]), "=r"(r[2]), "=r"(r[3]) : "r"(a));
}
__device__ __forceinline__ void mma16(float* c, const uint32_t* a, const uint32_t* b) {
    asm volatile(
        "mma.sync.aligned.m16n8k16.row.col.f32.f16.f16.f32 "
        "{%0,%1,%2,%3},{%4,%5,%6,%7},{%8,%9},{%0,%1,%2,%3};"
        : "+f"(c[0]), "+f"(c[1]), "+f"(c[2]), "+f"(c[3])
        : "r"(a[0]), "r"(a[1]), "r"(a[2]), "r"(a[3]), "r"(b[0]), "r"(b[1]));
}
// D = A*B + 0
__device__ __forceinline__ void mma16z(float* c, const uint32_t* a, const uint32_t* b) {
    asm volatile(
        "mma.sync.aligned.m16n8k16.row.col.f32.f16.f16.f32 "
        "{%0,%1,%2,%3},{%4,%5,%6,%7},{%8,%9},{%10,%10,%10,%10};"
        : "=f"(c[0]), "=f"(c[1]), "=f"(c[2]), "=f"(c[3])
        : "r"(a[0]), "r"(a[1]), "r"(a[2]), "r"(a[3]), "r"(b[0]), "r"(b[1]),
          "f"(0.f));
}
__device__ __forceinline__ __half2 f22h(float x, float y) {
    return __float22half2_rn(make_float2(x, y));
}
__device__ __forceinline__ uint32_t f22hu(float x, float y) {
    __half2 h = __float22half2_rn(make_float2(x, y));
    return *(uint32_t*)&h;
}
__device__ __forceinline__ float ex2(float x) {
    float r; asm("ex2.approx.f32 %0, %1;" : "=f"(r) : "f"(x)); return r;
}
__device__ __forceinline__ void cpa16(uint32_t d, const void* s) {
    asm volatile("cp.async.cg.shared.global [%0], [%1], 16;" :: "r"(d), "l"(s));
}
__device__ __forceinline__ void cpa4(uint32_t d, const void* s) {
    asm volatile("cp.async.ca.shared.global [%0], [%1], 4;" :: "r"(d), "l"(s));
}
#define CP_COMMIT() asm volatile("cp.async.commit_group;")
#define CP_WAIT1()  asm volatile("cp.async.wait_group 1;")

// ---------------------------------------------------------------------------
// Kernel 0: convert X, Wq, Wk, Wv to fp16 scratch. (unchanged)
// ---------------------------------------------------------------------------
__global__ __launch_bounds__(256) void to_half(
    const float* __restrict__ X, const float* __restrict__ Wq,
    const float* __restrict__ Wk, const float* __restrict__ Wv)
{
    const int XG = (Bsz*SEQ*HID) / 4;
    const int WG = (HID*HID) / 4;
    int idx = blockIdx.x * blockDim.x + threadIdx.x;
    const float4* src;
    __half* dst;
    if (idx < XG)             { src = (const float4*)X  + idx;               dst = g_xh + (size_t)idx * 4; }
    else if (idx < XG + WG)   { src = (const float4*)Wq + (idx - XG);        dst = g_wh + (size_t)(idx - XG) * 4; }
    else if (idx < XG + 2*WG) { src = (const float4*)Wk + (idx - XG - WG);   dst = g_wh + (size_t)HID*HID + (size_t)(idx - XG - WG) * 4; }
    else if (idx < XG + 3*WG) { src = (const float4*)Wv + (idx - XG - 2*WG); dst = g_wh + (size_t)2*HID*HID + (size_t)(idx - XG - 2*WG) * 4; }
    else return;
    float4 v = *src;
    uint2 pack;
    pack.x = f22hu(v.x, v.y);
    pack.y = f22hu(v.z, v.w);
    *(uint2*)dst = pack;
}

// ---------------------------------------------------------------------------
// Kernel 1: fused QKV projection (unchanged from R14).
// ---------------------------------------------------------------------------
#define QKV_SMEM 87552

__global__ __launch_bounds__(512) void qkv_gemm(
    const float* __restrict__ bq, const float* __restrict__ bk,
    const float* __restrict__ bv)
{
    extern __shared__ __align__(16) __half qsm[];
    const uint32_t qb = sptr(qsm);
    const uint32_t BsBase = qb + 3 * 20480;

    const int tid  = threadIdx.x;
    const int warp = tid >> 5;
    const int lane = tid & 31;
    const int g    = lane >> 2;
    const int tig  = lane & 3;

    const int row0   = blockIdx.y * 256;
    const int colblk = blockIdx.x;
    const int sel    = colblk >> 3;
    const int ncol   = (colblk & 7) * 128;

    const __half* Wh  = g_wh + (size_t)sel * HID * HID;
    const float* bias = (sel == 0) ? bq : (sel == 1) ? bk : bv;
    __half*      dst  = (sel == 0) ? g_q : (sel == 1) ? g_k : g_v;

    const int wm = (warp >> 2) * 64;
    const int wn = (warp & 3) * 32;

    float acc[4][4][4];
#pragma unroll
    for (int i = 0; i < 4; i++)
#pragma unroll
        for (int j = 0; j < 4; j++)
#pragma unroll
            for (int k = 0; k < 4; k++) acc[i][j][k] = 0.f;

    const int lrow = ((lane >> 3) & 1) * 8 + (lane & 7);
    const int lk8  = (lane >> 4) * 8;

    const int ar  = tid >> 2;
    const int ac8 = (tid & 3) * 8;
    const int br  = tid >> 4;
    const int bc8 = (tid & 15) * 8;
    const uint32_t asm0 = (uint32_t)(ar * 40 + ac8) * 2;
    const uint32_t asm1 = (uint32_t)((ar + 128) * 40 + ac8) * 2;
    const uint32_t bsm0 = (uint32_t)(br * 136 + bc8) * 2;
    const __half* ag0 = g_xh + (size_t)(row0 + ar) * HID + ac8;
    const __half* ag1 = g_xh + (size_t)(row0 + ar + 128) * HID + ac8;
    const __half* bg0 = Wh + (size_t)br * HID + ncol + bc8;

#pragma unroll
    for (int p = 0; p < 2; p++) {
        const int k0 = p * 32;
        const uint32_t AsB = qb + p * 20480;
        const uint32_t BsB = BsBase + p * 8704;
        cpa16(AsB + asm0, ag0 + k0);
        cpa16(AsB + asm1, ag1 + k0);
        cpa16(BsB + bsm0, bg0 + (size_t)k0 * HID);
        CP_COMMIT();
    }

    for (int ki = 0; ki < 32; ki++) {
        const int st = ki % 3;
        CP_WAIT1();
        __syncthreads();
        if (ki < 30) {
            const int k0 = (ki + 2) * 32;
            const int ns = (ki + 2) % 3;
            const uint32_t AsB = qb + ns * 20480;
            const uint32_t BsB = BsBase + ns * 8704;
            cpa16(AsB + asm0, ag0 + k0);
            cpa16(AsB + asm1, ag1 + k0);
            cpa16(BsB + bsm0, bg0 + (size_t)k0 * HID);
            CP_COMMIT();
        }
        const uint32_t AsB = qb + st * 20480;
        const uint32_t BsB = BsBase + st * 8704;

#pragma unroll
        for (int ks = 0; ks < 2; ks++) {
            const int kb = ks * 16;
            uint32_t a[4][4];
#pragma unroll
            for (int mt = 0; mt < 4; mt++)
                ldsm4(a[mt], AsB + (uint32_t)((wm + mt * 16 + lrow) * 40 + kb + lk8) * 2);
            uint32_t b[2][4];
#pragma unroll
            for (int nb = 0; nb < 2; nb++)
                ldsm4t(b[nb], BsB + (uint32_t)((kb + lrow) * 136 + wn + nb * 16 + lk8) * 2);
#pragma unroll
            for (int mt = 0; mt < 4; mt++)
#pragma unroll
                for (int nt = 0; nt < 4; nt++)
                    mma16(acc[mt][nt], a[mt], &b[nt >> 1][(nt & 1) * 2]);
        }
    }

    const int bidx = row0 >> 11;
#pragma unroll
    for (int mt = 0; mt < 4; mt++) {
        int r0 = row0 + wm + mt * 16 + g;
        int s0 = r0 & (SEQ - 1);
#pragma unroll
        for (int nt = 0; nt < 4; nt++) {
            int cc = wn + nt * 8 + 2 * tig;
            int h  = (ncol + cc) >> 6;
            int d  = (ncol + cc) & 63;
            float bf0 = bias[ncol + cc], bf1 = bias[ncol + cc + 1];
            __half* p = dst + (((size_t)bidx * NH + h) * SEQ + s0) * HD + d;
            *(__half2*)p            = f22h(acc[mt][nt][0] + bf0, acc[mt][nt][1] + bf1);
            *(__half2*)(p + 8 * HD) = f22h(acc[mt][nt][2] + bf0, acc[mt][nt][3] + bf1);
        }
    }
}

// ---------------------------------------------------------------------------
// Kernel 2: flash attention. Br=64, Bc=64, 256 threads = 8 warps (4 row x 2 col),
// 16 q-rows per warp. Deferred-max split-k, in-register P, hoisted Q frags,
// 3-stage cp.async, zero-C S mma, ballot-skipped O rescale.
// ~110 regs/thread -> 2 blocks/SM = 16 warps/SM.
// Smem: Qs 9216 | K 3x9216 | V 3x9216 | Ms 3x64f | RM 128f | RS 128f = 66304B
// ---------------------------------------------------------------------------
#define FA_SMEM 66304

__global__ __launch_bounds__(256, 2) void flash_attn(
    const float* __restrict__ mask, float* __restrict__ out)
{
    extern __shared__ __align__(16) __half dsm[];
    const uint32_t sb  = sptr(dsm);
    const uint32_t KbB = sb + 9216;
    const uint32_t VbB = sb + 9216 + 27648;
    const uint32_t MsB = sb + 64512;
    float* Ms = (float*)((char*)dsm + 64512);
    float* RM = (float*)((char*)dsm + 65280);
    float* RS = (float*)((char*)dsm + 65792);

    const int b  = blockIdx.z;
    const int h  = blockIdx.y;
    const int q0 = blockIdx.x * 64;

    const int tid  = threadIdx.x;
    const int warp = tid >> 5;
    const int lane = tid & 31;
    const int g    = lane >> 2;
    const int tig  = lane & 3;
    const int wr   = warp >> 1;      // 0..3
    const int wc   = warp & 1;
    const int qr   = wr * 16;        // 16 q-rows per warp
    const int scb  = wc * 32;

    const int lrow = ((lane >> 3) & 1) * 8 + (lane & 7);
    const int lk8  = (lane >> 4) * 8;
    const int bn   = (lane >> 4) * 8 + (lane & 7);
    const int bk8  = ((lane >> 3) & 1) * 8;

    const __half* Qg = g_q + ((size_t)(b * NH + h) * SEQ) * HD;
    const __half* Kg = g_k + ((size_t)(b * NH + h) * SEQ) * HD;
    const __half* Vg = g_v + ((size_t)(b * NH + h) * SEQ) * HD;
    const float*  mk = mask + b * SEQ;

    // Hoisted prefetch addressing (2 chunks per thread at 256 threads)
    uint32_t psm[2];
    int      pge[2];
#pragma unroll
    for (int i = 0; i < 2; i++) {
        int lin = tid + i * 256;
        int r   = lin >> 3;
        int c8  = (lin & 7) * 8;
        psm[i] = (uint32_t)(r * 72 + c8) * 2;
        pge[i] = r * HD + c8;
    }

    // Prologue: group0 = Q + K0 + V0 + M0 ; group1 = K1 + V1 + M1
#pragma unroll
    for (int i = 0; i < 2; i++) {
        cpa16(sb  + psm[i], &Qg[(size_t)q0 * HD + pge[i]]);
        cpa16(KbB + psm[i], &Kg[pge[i]]);
        cpa16(VbB + psm[i], &Vg[pge[i]]);
    }
    if (tid < 64) cpa4(MsB + tid * 4, &mk[tid]);
    CP_COMMIT();
#pragma unroll
    for (int i = 0; i < 2; i++) {
        cpa16(KbB + 9216 + psm[i], &Kg[64 * HD + pge[i]]);
        cpa16(VbB + 9216 + psm[i], &Vg[64 * HD + pge[i]]);
    }
    if (tid < 64) cpa4(MsB + (64 + tid) * 4, &mk[64 + tid]);
    CP_COMMIT();

    CP_WAIT1();
    __syncthreads();

    // Hoist Q fragments (16 rows -> one m16 tile per warp)
    uint32_t aq[4][4];
#pragma unroll
    for (int kk = 0; kk < 4; kk++)
        ldsm4(aq[kk], sb + (uint32_t)((qr + lrow) * 72 + kk * 16 + lk8) * 2);

    float o[8][4];
#pragma unroll
    for (int nt = 0; nt < 8; nt++)
#pragma unroll
        for (int j = 0; j < 4; j++) o[nt][j] = 0.f;

    float mrow[2] = {-1e30f, -1e30f};
    float lrowv[2] = {0.f, 0.f};
    const float C1  = 0.18033688011112042f;     // 0.125 * log2(e)
    const float L2E = 1.4426950408889634f;

    for (int it = 0; it < 32; it++) {
        const int st = it % 3;
        if (it > 0) {
            CP_WAIT1();
            __syncthreads();
        }
        if (it < 30) {
            const int ns = (it + 2) % 3;
            const int kc = (it + 2) * 64;
            const uint32_t kso = (uint32_t)(ns * 9216);
#pragma unroll
            for (int i = 0; i < 2; i++) {
                cpa16(KbB + kso + psm[i], &Kg[(size_t)kc * HD + pge[i]]);
                cpa16(VbB + kso + psm[i], &Vg[(size_t)kc * HD + pge[i]]);
            }
            if (tid < 64) cpa4(MsB + (ns * 64 + tid) * 4, &mk[kc + tid]);
            CP_COMMIT();
        }
        const uint32_t Ku = KbB + st * 9216;
        const uint32_t Vu = VbB + st * 9216;
        const float* Mb = Ms + st * 64;

        // ---- S = Q K^T : 16x32 per warp, kk=0 zero-C ----
        float s[4][4];
        {
            uint32_t bm[2][4];
            ldsm4(bm[0], Ku + (uint32_t)((scb      + bn) * 72 + bk8) * 2);
            ldsm4(bm[1], Ku + (uint32_t)((scb + 16 + bn) * 72 + bk8) * 2);
#pragma unroll
            for (int nt = 0; nt < 4; nt++)
                mma16z(s[nt], aq[0], &bm[nt >> 1][(nt & 1) * 2]);
        }
#pragma unroll
        for (int kk = 1; kk < 4; kk++) {
            const int kb = kk * 16;
            uint32_t bm[2][4];
            ldsm4(bm[0], Ku + (uint32_t)((scb      + bn) * 72 + kb + bk8) * 2);
            ldsm4(bm[1], Ku + (uint32_t)((scb + 16 + bn) * 72 + kb + bk8) * 2);
#pragma unroll
            for (int nt = 0; nt < 4; nt++)
                mma16(s[nt], aq[kk], &bm[nt >> 1][(nt & 1) * 2]);
        }

        // ---- warp-local scale + mask + row max ----
        float rm[2] = {-1e30f, -1e30f};
#pragma unroll
        for (int nt = 0; nt < 4; nt++) {
            int col = scb + nt * 8 + 2 * tig;
            float mv0 = Mb[col] * L2E, mv1 = Mb[col + 1] * L2E;
            s[nt][0] = s[nt][0] * C1 + mv0;
            s[nt][1] = s[nt][1] * C1 + mv1;
            s[nt][2] = s[nt][2] * C1 + mv0;
            s[nt][3] = s[nt][3] * C1 + mv1;
            rm[0] = fmaxf(rm[0], fmaxf(s[nt][0], s[nt][1]));
            rm[1] = fmaxf(rm[1], fmaxf(s[nt][2], s[nt][3]));
        }
        float alpha[2];
#pragma unroll
        for (int hh = 0; hh < 2; hh++) {
            rm[hh] = fmaxf(rm[hh], __shfl_xor_sync(0xffffffffu, rm[hh], 1));
            rm[hh] = fmaxf(rm[hh], __shfl_xor_sync(0xffffffffu, rm[hh], 2));
            float mn = fmaxf(mrow[hh], rm[hh]);
            alpha[hh] = ex2(mrow[hh] - mn);
            mrow[hh] = mn;
        }

        // ---- exp2 + P pack + l update ----
        float sum[2] = {0.f, 0.f};
        uint32_t ap[2][4];
#pragma unroll
        for (int nt = 0; nt < 4; nt++) {
            float p0 = ex2(s[nt][0] - mrow[0]);
            float p1 = ex2(s[nt][1] - mrow[0]);
            float p2 = ex2(s[nt][2] - mrow[1]);
            float p3 = ex2(s[nt][3] - mrow[1]);
            sum[0] += p0 + p1;
            sum[1] += p2 + p3;
            const int kk = nt >> 1;
            if (nt & 1) {
                ap[kk][2] = f22hu(p0, p1);
                ap[kk][3] = f22hu(p2, p3);
            } else {
                ap[kk][0] = f22hu(p0, p1);
                ap[kk][1] = f22hu(p2, p3);
            }
        }
#pragma unroll
        for (int hh = 0; hh < 2; hh++) {
            sum[hh] += __shfl_xor_sync(0xffffffffu, sum[hh], 1);
            sum[hh] += __shfl_xor_sync(0xffffffffu, sum[hh], 2);
            lrowv[hh] = lrowv[hh] * alpha[hh] + sum[hh];
        }

        // ---- O rescale, skipped when all alphas exactly 1 ----
        bool need = (alpha[0] < 1.f) | (alpha[1] < 1.f);
        if (__ballot_sync(0xffffffffu, need)) {
#pragma unroll
            for (int nt = 0; nt < 8; nt++) {
                o[nt][0] *= alpha[0];
                o[nt][1] *= alpha[0];
                o[nt][2] *= alpha[1];
                o[nt][3] *= alpha[1];
            }
        }

        // ---- O += P V (k-half = this warp's S cols) ----
#pragma unroll
        for (int kk = 0; kk < 2; kk++) {
            const int kbg = scb + kk * 16;
#pragma unroll
            for (int db = 0; db < 4; db++) {
                uint32_t bv4[4];
                ldsm4t(bv4, Vu + (uint32_t)((kbg + lrow) * 72 + db * 16 + lk8) * 2);
                mma16(o[db * 2    ], ap[kk], &bv4[0]);
                mma16(o[db * 2 + 1], ap[kk], &bv4[2]);
            }
        }
    }

    // ---- final combine: merge (O, m, l) across the two col-half warps ----
    float* cb = (float*)dsm;   // 64 x 68 f32 overlay (Q + K stage0 dead)
    __syncthreads();
    if (wc == 1) {
#pragma unroll
        for (int nt = 0; nt < 8; nt++) {
            int r0  = qr + g;
            int col = nt * 8 + 2 * tig;
            *(float2*)&cb[r0 * 68 + col]       = make_float2(o[nt][0], o[nt][1]);
            *(float2*)&cb[(r0 + 8) * 68 + col] = make_float2(o[nt][2], o[nt][3]);
        }
        if (tig == 0) {
#pragma unroll
            for (int hh = 0; hh < 2; hh++) {
                int row = qr + g + hh * 8;
                RM[row] = mrow[hh];
                RS[row] = lrowv[hh];
            }
        }
    }
    __syncthreads();
    if (wc == 0) {
        float sc0[2], sc1[2], inv[2];
#pragma unroll
        for (int hh = 0; hh < 2; hh++) {
            int row = qr + g + hh * 8;
            float m1 = RM[row], l1 = RS[row];
            float M  = fmaxf(mrow[hh], m1);
            sc0[hh] = ex2(mrow[hh] - M);
            sc1[hh] = ex2(m1 - M);
            inv[hh] = 1.f / (lrowv[hh] * sc0[hh] + l1 * sc1[hh]);
        }
        int r0 = qr + g;
        float* p0 = out + ((size_t)(b * SEQ + q0 + r0    )) * HID + h * HD;
        float* p1 = out + ((size_t)(b * SEQ + q0 + r0 + 8)) * HID + h * HD;
#pragma unroll
        for (int nt = 0; nt < 8; nt++) {
            int col = nt * 8 + 2 * tig;
            float2 e0 = *(float2*)&cb[r0 * 68 + col];
            float2 e1 = *(float2*)&cb[(r0 + 8) * 68 + col];
            *(float2*)&p0[col] = make_float2(
                (o[nt][0] * sc0[0] + e0.x * sc1[0]) * inv[0],
                (o[nt][1] * sc0[0] + e0.y * sc1[0]) * inv[0]);
            *(float2*)&p1[col] = make_float2(
                (o[nt][2] * sc0[1] + e1.x * sc1[1]) * inv[1],
                (o[nt][3] * sc0[1] + e1.y * sc1[1]) * inv[1]);
        }
    }
}

// ---------------------------------------------------------------------------
extern "C" void kernel_launch(void* const* d_in, const int* in_sizes, int n_in,
                              void* d_out, int out_size)
{
    const float* X    = (const float*)d_in[0];
    const float* mask = (const float*)d_in[1];
    const float* Wq   = (const float*)d_in[2];
    const float* bq   = (const float*)d_in[3];
    const float* Wk   = (const float*)d_in[4];
    const float* bk   = (const float*)d_in[5];
    const float* Wv   = (const float*)d_in[6];
    const float* bv   = (const float*)d_in[7];
    float* out = (float*)d_out;

    cudaFuncSetAttribute(flash_attn, cudaFuncAttributeMaxDynamicSharedMemorySize,
                         FA_SMEM);
    cudaFuncSetAttribute(qkv_gemm, cudaFuncAttributeMaxDynamicSharedMemorySize,
                         QKV_SMEM);

    const int XG = (Bsz*SEQ*HID) / 4;
    const int WG = (HID*HID) / 4;
    int cvt_blocks = (XG + 3 * WG + 255) / 256;
    to_half<<<cvt_blocks, 256>>>(X, Wq, Wk, Wv);

    dim3 g1(24, 32);
    qkv_gemm<<<g1, 512, QKV_SMEM>>>(bq, bk, bv);

    dim3 g2(32, NH, Bsz);
    flash_attn<<<g2, 256, FA_SMEM>>>(mask, out);
}

// round 17
// speedup vs baseline: 1.1272x; 1.1272x over previous
#include <cuda_runtime.h>
#include <cuda_fp16.h>
#include <math.h>
#include <stdint.h>

#define Bsz 4
#define SEQ 2048
#define HID 1024
#define NH 16
#define HD 64

// fp16 scratch
__device__ __half g_q[Bsz*NH*SEQ*HD];
__device__ __half g_k[Bsz*NH*SEQ*HD];
__device__ __half g_v[Bsz*NH*SEQ*HD];
__device__ __half g_xh[(size_t)Bsz*SEQ*HID];
__device__ __half g_wh[3*HID*HID];

// ---------------------------------------------------------------------------
__device__ __forceinline__ uint32_t sptr(const void* p) {
    return (uint32_t)__cvta_generic_to_shared(p);
}
__device__ __forceinline__ void ldsm4(uint32_t* r, uint32_t a) {
    asm volatile("ldmatrix.sync.aligned.m8n8.x4.shared.b16 {%0,%1,%2,%3}, [%4];"
        : "=r"(r[0]), "=r"(r[1]), "=r"(r[2]), "=r"(r[3]) : "r"(a));
}
__device__ __forceinline__ void ldsm4t(uint32_t* r, uint32_t a) {
    asm volatile("ldmatrix.sync.aligned.m8n8.x4.trans.shared.b16 {%0,%1,%2,%3}, [%4];"
        : "=r"(r[0]), "=r"(r[1]), "=r"(r[2]), "=r"(r[3]) : "r"(a));
}
__device__ __forceinline__ void mma16(float* c, const uint32_t* a, const uint32_t* b) {
    asm volatile(
        "mma.sync.aligned.m16n8k16.row.col.f32.f16.f16.f32 "
        "{%0,%1,%2,%3},{%4,%5,%6,%7},{%8,%9},{%0,%1,%2,%3};"
        : "+f"(c[0]), "+f"(c[1]), "+f"(c[2]), "+f"(c[3])
        : "r"(a[0]), "r"(a[1]), "r"(a[2]), "r"(a[3]), "r"(b[0]), "r"(b[1]));
}
// D = A*B + 0
__device__ __forceinline__ void mma16z(float* c, const uint32_t* a, const uint32_t* b) {
    asm volatile(
        "mma.sync.aligned.m16n8k16.row.col.f32.f16.f16.f32 "
        "{%0,%1,%2,%3},{%4,%5,%6,%7},{%8,%9},{%10,%10,%10,%10};"
        : "=f"(c[0]), "=f"(c[1]), "=f"(c[2]), "=f"(c[3])
        : "r"(a[0]), "r"(a[1]), "r"(a[2]), "r"(a[3]), "r"(b[0]), "r"(b[1]),
          "f"(0.f));
}
__device__ __forceinline__ __half2 f22h(float x, float y) {
    return __float22half2_rn(make_float2(x, y));
}
__device__ __forceinline__ uint32_t f22hu(float x, float y) {
    __half2 h = __float22half2_rn(make_float2(x, y));
    return *(uint32_t*)&h;
}
__device__ __forceinline__ float ex2(float x) {
    float r; asm("ex2.approx.f32 %0, %1;" : "=f"(r) : "f"(x)); return r;
}
__device__ __forceinline__ void cpa16(uint32_t d, const void* s) {
    asm volatile("cp.async.cg.shared.global [%0], [%1], 16;" :: "r"(d), "l"(s));
}
__device__ __forceinline__ void cpa4(uint32_t d, const void* s) {
    asm volatile("cp.async.ca.shared.global [%0], [%1], 4;" :: "r"(d), "l"(s));
}
#define CP_COMMIT() asm volatile("cp.async.commit_group;")
#define CP_WAIT1()  asm volatile("cp.async.wait_group 1;")

// ---------------------------------------------------------------------------
// Kernel 0: convert X, Wq, Wk, Wv to fp16 scratch. (unchanged)
// ---------------------------------------------------------------------------
__global__ __launch_bounds__(256) void to_half(
    const float* __restrict__ X, const float* __restrict__ Wq,
    const float* __restrict__ Wk, const float* __restrict__ Wv)
{
    const int XG = (Bsz*SEQ*HID) / 4;
    const int WG = (HID*HID) / 4;
    int idx = blockIdx.x * blockDim.x + threadIdx.x;
    const float4* src;
    __half* dst;
    if (idx < XG)             { src = (const float4*)X  + idx;               dst = g_xh + (size_t)idx * 4; }
    else if (idx < XG + WG)   { src = (const float4*)Wq + (idx - XG);        dst = g_wh + (size_t)(idx - XG) * 4; }
    else if (idx < XG + 2*WG) { src = (const float4*)Wk + (idx - XG - WG);   dst = g_wh + (size_t)HID*HID + (size_t)(idx - XG - WG) * 4; }
    else if (idx < XG + 3*WG) { src = (const float4*)Wv + (idx - XG - 2*WG); dst = g_wh + (size_t)2*HID*HID + (size_t)(idx - XG - 2*WG) * 4; }
    else return;
    float4 v = *src;
    uint2 pack;
    pack.x = f22hu(v.x, v.y);
    pack.y = f22hu(v.z, v.w);
    *(uint2*)dst = pack;
}

// ---------------------------------------------------------------------------
// Kernel 1: fused QKV projection, fp16, BM=256 x BN=128, BK=64 per stage,
// 512 threads, 3-stage cp.async (wait_group 1), 16 mainloop iterations.
// smem: As 3 x [256][72]h (36864B) | Bs 3 x [64][136]h (17408B) = 162816B
// ---------------------------------------------------------------------------
#define QKV_SMEM 162816

__global__ __launch_bounds__(512) void qkv_gemm(
    const float* __restrict__ bq, const float* __restrict__ bk,
    const float* __restrict__ bv)
{
    extern __shared__ __align__(16) __half qsm[];
    const uint32_t qb = sptr(qsm);
    const uint32_t BsBase = qb + 3 * 36864;

    const int tid  = threadIdx.x;
    const int warp = tid >> 5;
    const int lane = tid & 31;
    const int g    = lane >> 2;
    const int tig  = lane & 3;

    const int row0   = blockIdx.y * 256;
    const int colblk = blockIdx.x;
    const int sel    = colblk >> 3;
    const int ncol   = (colblk & 7) * 128;

    const __half* Wh  = g_wh + (size_t)sel * HID * HID;
    const float* bias = (sel == 0) ? bq : (sel == 1) ? bk : bv;
    __half*      dst  = (sel == 0) ? g_q : (sel == 1) ? g_k : g_v;

    const int wm = (warp >> 2) * 64;
    const int wn = (warp & 3) * 32;

    float acc[4][4][4];
#pragma unroll
    for (int i = 0; i < 4; i++)
#pragma unroll
        for (int j = 0; j < 4; j++)
#pragma unroll
            for (int k = 0; k < 4; k++) acc[i][j][k] = 0.f;

    const int lrow = ((lane >> 3) & 1) * 8 + (lane & 7);
    const int lk8  = (lane >> 4) * 8;

    // Hoisted prefetch addressing: A 4 chunks/thread, B 2 chunks/thread
    uint32_t pa[4];
    const __half* pag[4];
#pragma unroll
    for (int i = 0; i < 4; i++) {
        int lin = tid + i * 512;          // 0..2047
        int r   = lin >> 3;               // 0..255
        int c8  = (lin & 7) * 8;          // 0..56
        pa[i]  = (uint32_t)(r * 72 + c8) * 2;
        pag[i] = g_xh + (size_t)(row0 + r) * HID + c8;
    }
    uint32_t pb[2];
    const __half* pbg[2];
#pragma unroll
    for (int i = 0; i < 2; i++) {
        int lin = tid + i * 512;          // 0..1023
        int r   = lin >> 4;               // 0..63
        int c8  = (lin & 15) * 8;         // 0..120
        pb[i]  = (uint32_t)(r * 136 + c8) * 2;
        pbg[i] = Wh + (size_t)r * HID + ncol + c8;
    }

    // prologue: stages ki=0, ki=1
#pragma unroll
    for (int p = 0; p < 2; p++) {
        const int k0 = p * 64;
        const uint32_t AsB = qb + p * 36864;
        const uint32_t BsB = BsBase + p * 17408;
#pragma unroll
        for (int i = 0; i < 4; i++) cpa16(AsB + pa[i], pag[i] + k0);
#pragma unroll
        for (int i = 0; i < 2; i++) cpa16(BsB + pb[i], pbg[i] + (size_t)k0 * HID);
        CP_COMMIT();
    }

    for (int ki = 0; ki < 16; ki++) {
        const int st = ki % 3;
        CP_WAIT1();
        __syncthreads();
        if (ki < 14) {
            const int k0 = (ki + 2) * 64;
            const int ns = (ki + 2) % 3;
            const uint32_t AsB = qb + ns * 36864;
            const uint32_t BsB = BsBase + ns * 17408;
#pragma unroll
            for (int i = 0; i < 4; i++) cpa16(AsB + pa[i], pag[i] + k0);
#pragma unroll
            for (int i = 0; i < 2; i++) cpa16(BsB + pb[i], pbg[i] + (size_t)k0 * HID);
            CP_COMMIT();
        }
        const uint32_t AsB = qb + st * 36864;
        const uint32_t BsB = BsBase + st * 17408;

#pragma unroll
        for (int ks = 0; ks < 4; ks++) {
            const int kb = ks * 16;
            uint32_t a[4][4];
#pragma unroll
            for (int mt = 0; mt < 4; mt++)
                ldsm4(a[mt], AsB + (uint32_t)((wm + mt * 16 + lrow) * 72 + kb + lk8) * 2);
            uint32_t b[2][4];
#pragma unroll
            for (int nb = 0; nb < 2; nb++)
                ldsm4t(b[nb], BsB + (uint32_t)((kb + lrow) * 136 + wn + nb * 16 + lk8) * 2);
#pragma unroll
            for (int mt = 0; mt < 4; mt++)
#pragma unroll
                for (int nt = 0; nt < 4; nt++)
                    mma16(acc[mt][nt], a[mt], &b[nt >> 1][(nt & 1) * 2]);
        }
    }

    const int bidx = row0 >> 11;
#pragma unroll
    for (int mt = 0; mt < 4; mt++) {
        int r0 = row0 + wm + mt * 16 + g;
        int s0 = r0 & (SEQ - 1);
#pragma unroll
        for (int nt = 0; nt < 4; nt++) {
            int cc = wn + nt * 8 + 2 * tig;
            int h  = (ncol + cc) >> 6;
            int d  = (ncol + cc) & 63;
            float bf0 = bias[ncol + cc], bf1 = bias[ncol + cc + 1];
            __half* p = dst + (((size_t)bidx * NH + h) * SEQ + s0) * HD + d;
            *(__half2*)p            = f22h(acc[mt][nt][0] + bf0, acc[mt][nt][1] + bf1);
            *(__half2*)(p + 8 * HD) = f22h(acc[mt][nt][2] + bf0, acc[mt][nt][3] + bf1);
        }
    }
}

// ---------------------------------------------------------------------------
// Kernel 2: flash attention — EXACT R14 champion version.
// Br=64, Bc=64, 128 threads, 4 warps (2 row x 2 col), 32 q-rows per warp.
// Deferred-max split-k, in-register P, hoisted Q frags, 3-stage cp.async,
// zero-C S mma, ballot-skipped O rescale, hoisted prefetch addressing.
// Smem: Qs 9216 | K 3x9216 | V 3x9216 | Ms 3x64f | RM 128f | RS 128f = 66304B
// ---------------------------------------------------------------------------
#define FA_SMEM 66304

__global__ __launch_bounds__(128, 3) void flash_attn(
    const float* __restrict__ mask, float* __restrict__ out)
{
    extern __shared__ __align__(16) __half dsm[];
    const uint32_t sb  = sptr(dsm);
    const uint32_t KbB = sb + 9216;
    const uint32_t VbB = sb + 9216 + 27648;
    const uint32_t MsB = sb + 64512;
    float* Ms = (float*)((char*)dsm + 64512);
    float* RM = (float*)((char*)dsm + 65280);
    float* RS = (float*)((char*)dsm + 65792);

    const int b  = blockIdx.z;
    const int h  = blockIdx.y;
    const int q0 = blockIdx.x * 64;

    const int tid  = threadIdx.x;
    const int warp = tid >> 5;
    const int lane = tid & 31;
    const int g    = lane >> 2;
    const int tig  = lane & 3;
    const int wr   = warp >> 1;
    const int wc   = warp & 1;
    const int qr   = wr * 32;
    const int scb  = wc * 32;

    const int lrow = ((lane >> 3) & 1) * 8 + (lane & 7);
    const int lk8  = (lane >> 4) * 8;
    const int bn   = (lane >> 4) * 8 + (lane & 7);
    const int bk8  = ((lane >> 3) & 1) * 8;

    const __half* Qg = g_q + ((size_t)(b * NH + h) * SEQ) * HD;
    const __half* Kg = g_k + ((size_t)(b * NH + h) * SEQ) * HD;
    const __half* Vg = g_v + ((size_t)(b * NH + h) * SEQ) * HD;
    const float*  mk = mask + b * SEQ;

    // Hoisted prefetch addressing
    uint32_t psm[4];
    int      pge[4];
#pragma unroll
    for (int i = 0; i < 4; i++) {
        int lin = tid + i * 128;
        int r   = lin >> 3;
        int c8  = (lin & 7) * 8;
        psm[i] = (uint32_t)(r * 72 + c8) * 2;
        pge[i] = r * HD + c8;
    }

    // Prologue: group0 = Q + K0 + V0 + M0 ; group1 = K1 + V1 + M1
#pragma unroll
    for (int i = 0; i < 4; i++) {
        cpa16(sb  + psm[i], &Qg[(size_t)q0 * HD + pge[i]]);
        cpa16(KbB + psm[i], &Kg[pge[i]]);
        cpa16(VbB + psm[i], &Vg[pge[i]]);
    }
    if (tid < 64) cpa4(MsB + tid * 4, &mk[tid]);
    CP_COMMIT();
#pragma unroll
    for (int i = 0; i < 4; i++) {
        cpa16(KbB + 9216 + psm[i], &Kg[64 * HD + pge[i]]);
        cpa16(VbB + 9216 + psm[i], &Vg[64 * HD + pge[i]]);
    }
    if (tid < 64) cpa4(MsB + (64 + tid) * 4, &mk[64 + tid]);
    CP_COMMIT();

    CP_WAIT1();
    __syncthreads();

    // Hoist Q fragments (loop-invariant)
    uint32_t aq[2][4][4];
#pragma unroll
    for (int mt = 0; mt < 2; mt++)
#pragma unroll
        for (int kk = 0; kk < 4; kk++)
            ldsm4(aq[mt][kk], sb + (uint32_t)((qr + mt * 16 + lrow) * 72 + kk * 16 + lk8) * 2);

    float o[2][8][4];
#pragma unroll
    for (int mt = 0; mt < 2; mt++)
#pragma unroll
        for (int nt = 0; nt < 8; nt++)
#pragma unroll
            for (int j = 0; j < 4; j++) o[mt][nt][j] = 0.f;

    float mrow[2][2] = {{-1e30f, -1e30f}, {-1e30f, -1e30f}};
    float lrowv[2][2] = {{0.f, 0.f}, {0.f, 0.f}};
    const float C1  = 0.18033688011112042f;     // 0.125 * log2(e)
    const float L2E = 1.4426950408889634f;

    for (int it = 0; it < 32; it++) {
        const int st = it % 3;
        if (it > 0) {
            CP_WAIT1();
            __syncthreads();
        }
        if (it < 30) {
            const int ns = (it + 2) % 3;
            const int kc = (it + 2) * 64;
            const uint32_t kso = (uint32_t)(ns * 9216);
#pragma unroll
            for (int i = 0; i < 4; i++) {
                cpa16(KbB + kso + psm[i], &Kg[(size_t)kc * HD + pge[i]]);
                cpa16(VbB + kso + psm[i], &Vg[(size_t)kc * HD + pge[i]]);
            }
            if (tid < 64) cpa4(MsB + (ns * 64 + tid) * 4, &mk[kc + tid]);
            CP_COMMIT();
        }
        const uint32_t Ku = KbB + st * 9216;
        const uint32_t Vu = VbB + st * 9216;
        const float* Mb = Ms + st * 64;

        // ---- S = Q K^T : 32x32 per warp, kk=0 uses zero-C mma ----
        float s[2][4][4];
        {
            uint32_t bm[2][4];
            ldsm4(bm[0], Ku + (uint32_t)((scb      + bn) * 72 + bk8) * 2);
            ldsm4(bm[1], Ku + (uint32_t)((scb + 16 + bn) * 72 + bk8) * 2);
#pragma unroll
            for (int mt = 0; mt < 2; mt++)
#pragma unroll
                for (int nt = 0; nt < 4; nt++)
                    mma16z(s[mt][nt], aq[mt][0], &bm[nt >> 1][(nt & 1) * 2]);
        }
#pragma unroll
        for (int kk = 1; kk < 4; kk++) {
            const int kb = kk * 16;
            uint32_t bm[2][4];
            ldsm4(bm[0], Ku + (uint32_t)((scb      + bn) * 72 + kb + bk8) * 2);
            ldsm4(bm[1], Ku + (uint32_t)((scb + 16 + bn) * 72 + kb + bk8) * 2);
#pragma unroll
            for (int mt = 0; mt < 2; mt++)
#pragma unroll
                for (int nt = 0; nt < 4; nt++)
                    mma16(s[mt][nt], aq[mt][kk], &bm[nt >> 1][(nt & 1) * 2]);
        }

        // ---- warp-local scale + mask + row max ----
        float rm[2][2] = {{-1e30f, -1e30f}, {-1e30f, -1e30f}};
#pragma unroll
        for (int mt = 0; mt < 2; mt++)
#pragma unroll
            for (int nt = 0; nt < 4; nt++) {
                int col = scb + nt * 8 + 2 * tig;
                float mv0 = Mb[col] * L2E, mv1 = Mb[col + 1] * L2E;
                s[mt][nt][0] = s[mt][nt][0] * C1 + mv0;
                s[mt][nt][1] = s[mt][nt][1] * C1 + mv1;
                s[mt][nt][2] = s[mt][nt][2] * C1 + mv0;
                s[mt][nt][3] = s[mt][nt][3] * C1 + mv1;
                rm[mt][0] = fmaxf(rm[mt][0], fmaxf(s[mt][nt][0], s[mt][nt][1]));
                rm[mt][1] = fmaxf(rm[mt][1], fmaxf(s[mt][nt][2], s[mt][nt][3]));
            }
        float alpha[2][2];
#pragma unroll
        for (int mt = 0; mt < 2; mt++)
#pragma unroll
            for (int hh = 0; hh < 2; hh++) {
                rm[mt][hh] = fmaxf(rm[mt][hh], __shfl_xor_sync(0xffffffffu, rm[mt][hh], 1));
                rm[mt][hh] = fmaxf(rm[mt][hh], __shfl_xor_sync(0xffffffffu, rm[mt][hh], 2));
                float mn = fmaxf(mrow[mt][hh], rm[mt][hh]);
                alpha[mt][hh] = ex2(mrow[mt][hh] - mn);
                mrow[mt][hh] = mn;
            }

        // ---- exp2 + P pack + l update ----
        float sum[2][2] = {{0.f, 0.f}, {0.f, 0.f}};
        uint32_t ap[2][2][4];
#pragma unroll
        for (int mt = 0; mt < 2; mt++)
#pragma unroll
            for (int nt = 0; nt < 4; nt++) {
                float p0 = ex2(s[mt][nt][0] - mrow[mt][0]);
                float p1 = ex2(s[mt][nt][1] - mrow[mt][0]);
                float p2 = ex2(s[mt][nt][2] - mrow[mt][1]);
                float p3 = ex2(s[mt][nt][3] - mrow[mt][1]);
                sum[mt][0] += p0 + p1;
                sum[mt][1] += p2 + p3;
                const int kk = nt >> 1;
                if (nt & 1) {
                    ap[mt][kk][2] = f22hu(p0, p1);
                    ap[mt][kk][3] = f22hu(p2, p3);
                } else {
                    ap[mt][kk][0] = f22hu(p0, p1);
                    ap[mt][kk][1] = f22hu(p2, p3);
                }
            }
#pragma unroll
        for (int mt = 0; mt < 2; mt++)
#pragma unroll
            for (int hh = 0; hh < 2; hh++) {
                sum[mt][hh] += __shfl_xor_sync(0xffffffffu, sum[mt][hh], 1);
                sum[mt][hh] += __shfl_xor_sync(0xffffffffu, sum[mt][hh], 2);
                lrowv[mt][hh] = lrowv[mt][hh] * alpha[mt][hh] + sum[mt][hh];
            }

        // ---- O rescale, skipped when all alphas are exactly 1 ----
        bool need = (alpha[0][0] < 1.f) | (alpha[0][1] < 1.f)
                  | (alpha[1][0] < 1.f) | (alpha[1][1] < 1.f);
        if (__ballot_sync(0xffffffffu, need)) {
#pragma unroll
            for (int mt = 0; mt < 2; mt++)
#pragma unroll
                for (int nt = 0; nt < 8; nt++) {
                    o[mt][nt][0] *= alpha[mt][0];
                    o[mt][nt][1] *= alpha[mt][0];
                    o[mt][nt][2] *= alpha[mt][1];
                    o[mt][nt][3] *= alpha[mt][1];
                }
        }

        // ---- O += P V (k-half = this warp's S cols) ----
#pragma unroll
        for (int kk = 0; kk < 2; kk++) {
            const int kbg = scb + kk * 16;
#pragma unroll
            for (int db = 0; db < 4; db++) {
                uint32_t bv4[4];
                ldsm4t(bv4, Vu + (uint32_t)((kbg + lrow) * 72 + db * 16 + lk8) * 2);
                mma16(o[0][db * 2    ], ap[0][kk], &bv4[0]);
                mma16(o[1][db * 2    ], ap[1][kk], &bv4[0]);
                mma16(o[0][db * 2 + 1], ap[0][kk], &bv4[2]);
                mma16(o[1][db * 2 + 1], ap[1][kk], &bv4[2]);
            }
        }
    }

    // ---- final combine: merge (O, m, l) across the two col-half warps ----
    float* cb = (float*)dsm;
    __syncthreads();
    if (wc == 1) {
#pragma unroll
        for (int mt = 0; mt < 2; mt++) {
#pragma unroll
            for (int nt = 0; nt < 8; nt++) {
                int r0  = qr + mt * 16 + g;
                int col = nt * 8 + 2 * tig;
                *(float2*)&cb[r0 * 68 + col]       = make_float2(o[mt][nt][0], o[mt][nt][1]);
                *(float2*)&cb[(r0 + 8) * 68 + col] = make_float2(o[mt][nt][2], o[mt][nt][3]);
            }
            if (tig == 0) {
#pragma unroll
                for (int hh = 0; hh < 2; hh++) {
                    int row = qr + mt * 16 + g + hh * 8;
                    RM[row] = mrow[mt][hh];
                    RS[row] = lrowv[mt][hh];
                }
            }
        }
    }
    __syncthreads();
    if (wc == 0) {
#pragma unroll
        for (int mt = 0; mt < 2; mt++) {
            float sc0[2], sc1[2], inv[2];
#pragma unroll
            for (int hh = 0; hh < 2; hh++) {
                int row = qr + mt * 16 + g + hh * 8;
                float m1 = RM[row], l1 = RS[row];
                float M  = fmaxf(mrow[mt][hh], m1);
                sc0[hh] = ex2(mrow[mt][hh] - M);
                sc1[hh] = ex2(m1 - M);
                inv[hh] = 1.f / (lrowv[mt][hh] * sc0[hh] + l1 * sc1[hh]);
            }
            int r0 = qr + mt * 16 + g;
            float* p0 = out + ((size_t)(b * SEQ + q0 + r0    )) * HID + h * HD;
            float* p1 = out + ((size_t)(b * SEQ + q0 + r0 + 8)) * HID + h * HD;
#pragma unroll
            for (int nt = 0; nt < 8; nt++) {
                int col = nt * 8 + 2 * tig;
                float2 e0 = *(float2*)&cb[r0 * 68 + col];
                float2 e1 = *(float2*)&cb[(r0 + 8) * 68 + col];
                *(float2*)&p0[col] = make_float2(
                    (o[mt][nt][0] * sc0[0] + e0.x * sc1[0]) * inv[0],
                    (o[mt][nt][1] * sc0[0] + e0.y * sc1[0]) * inv[0]);
                *(float2*)&p1[col] = make_float2(
                    (o[mt][nt][2] * sc0[1] + e1.x * sc1[1]) * inv[1],
                    (o[mt][nt][3] * sc0[1] + e1.y * sc1[1]) * inv[1]);
            }
        }
    }
}

// ---------------------------------------------------------------------------
extern "C" void kernel_launch(void* const* d_in, const int* in_sizes, int n_in,
                              void* d_out, int out_size)
{
    const float* X    = (const float*)d_in[0];
    const float* mask = (const float*)d_in[1];
    const float* Wq   = (const float*)d_in[2];
    const float* bq   = (const float*)d_in[3];
    const float* Wk   = (const float*)d_in[4];
    const float* bk   = (const float*)d_in[5];
    const float* Wv   = (const float*)d_in[6];
    const float* bv   = (const float*)d_in[7];
    float* out = (float*)d_out;

    cudaFuncSetAttribute(flash_attn, cudaFuncAttributeMaxDynamicSharedMemorySize,
                         FA_SMEM);
    cudaFuncSetAttribute(qkv_gemm, cudaFuncAttributeMaxDynamicSharedMemorySize,
                         QKV_SMEM);

    const int XG = (Bsz*SEQ*HID) / 4;
    const int WG = (HID*HID) / 4;
    int cvt_blocks = (XG + 3 * WG + 255) / 256;
    to_half<<<cvt_blocks, 256>>>(X, Wq, Wk, Wv);

    dim3 g1(24, 32);
    qkv_gemm<<<g1, 512, QKV_SMEM>>>(bq, bk, bv);

    dim3 g2(32, NH, Bsz);
    flash_attn<<<g2, 128, FA_SMEM>>>(mask, out);
}